// round 1
// baseline (speedup 1.0000x reference)
#include <cuda_runtime.h>
#include <math.h>

// ---------------------------------------------------------------------------
// SplatPushModel2 — native-layout (no transposes) 5-kernel pipeline:
//   k_scalars : per-batch geometry + zero accumulators
//   k_reduce<0>: m_swept   = sum occ * swept          (band-culled)
//   k_reduce<1>: existing  = sum occ * probe          (band-culled, needs pile)
//   k_reduce<2>: dep_sum   = sum dep_mask             (no occ read)
//   k_final   : out = occ*(1-swept) + blur(dep_mask)*dep_norm
// Sigmoid cutoff CUT=16 -> dropped terms < e^-16 ~ 1.1e-7 (tol 1e-3).
// ---------------------------------------------------------------------------

#define NB   16
#define HW   1024
#define IMG  (HW*HW)

__device__ __constant__ float KW[9] = {
    0.00761439f, 0.03607498f, 0.10958593f, 0.21344431f, 0.26655960f,
    0.21344431f, 0.10958593f, 0.03607498f, 0.00761439f
};

struct Geo { float p0x, p0y, p1x, p1y, ux, uy, L, pad; };
__device__ Geo  g_geo[NB];
__device__ float g_msw[NB], g_ext[NB], g_dsum[NB];

__device__ __forceinline__ float clampf(float v, float lo, float hi) {
    return fminf(fmaxf(v, lo), hi);
}

// block-wide (256 thr) sum + atomic add; block-uniform call sites only
__device__ __forceinline__ void tileReduceAdd(float v, float* dst) {
    __shared__ float sred[8];
    #pragma unroll
    for (int o = 16; o > 0; o >>= 1) v += __shfl_down_sync(0xffffffffu, v, o);
    int lane = threadIdx.x & 31, wp = threadIdx.x >> 5;
    if (lane == 0) sred[wp] = v;
    __syncthreads();
    if (wp == 0) {
        v = (lane < 8) ? sred[lane] : 0.0f;
        #pragma unroll
        for (int o = 4; o > 0; o >>= 1) v += __shfl_down_sync(0xffffffffu, v, o);
        if (lane == 0) atomicAdd(dst, v);
    }
    __syncthreads();
}

__global__ void k_scalars(const float* __restrict__ as_, const float* __restrict__ ae_) {
    int b = threadIdx.x;
    if (b < NB) {
        float p0x = as_[b*3+0], p0y = as_[b*3+1];
        float p1x = ae_[b*3+0], p1y = ae_[b*3+1];
        float dx = p1x - p0x, dy = p1y - p0y;
        float L = sqrtf(dx*dx + dy*dy + 1e-8f);
        float inv = __fdividef(1.0f, L);
        Geo g;
        g.p0x = p0x; g.p0y = p0y; g.p1x = p1x; g.p1y = p1y;
        g.ux = dx*inv; g.uy = dy*inv; g.L = L; g.pad = 0.f;
        g_geo[b] = g;
        g_msw[b] = 0.f; g_ext[b] = 0.f; g_dsum[b] = 0.f;
    }
}

// MODE 0: m_swept; MODE 1: existing (probe); MODE 2: dep_sum (no occ)
template<int MODE>
__global__ __launch_bounds__(256) void k_reduce(const float* __restrict__ occ) {
    const float WIDTH = 3.0f, CUT = 16.0f, EPS = 1e-8f;
    const int TILES = NB * 32 * 32;   // 32x32-px tiles
    for (int tile = blockIdx.x; tile < TILES; tile += gridDim.x) {
        int b  = tile >> 10;
        int ti = tile & 1023;
        int tw = (ti & 31) << 5;
        int th = (ti >> 5) << 5;
        Geo g = g_geo[b];
        float pile = 0.f, extra = 0.f;
        if (MODE >= 1) pile  = g_msw[b] * (1.0f/6.0f);
        if (MODE == 2) extra = g_ext[b] * (1.0f/6.0f);

        float cx = tw + 15.5f, cy = th + 15.5f;
        bool active;
        if (MODE == 0) {
            float rx = cx - g.p0x, ry = cy - g.p0y;
            float t  = clampf(rx*g.ux + ry*g.uy, 0.f, g.L);
            float ddx = rx - t*g.ux, ddy = ry - t*g.uy;
            float d2 = ddx*ddx + ddy*ddy;
            float R  = WIDTH + CUT + 23.0f;   // + tile half-diag
            active = d2 < R*R;
        } else {
            float qx = cx - g.p1x, qy = cy - g.p1y;
            float s  = qx*g.ux + qy*g.uy;
            float r  = qy*g.ux - qx*g.uy;
            float he = 16.5f*(fabsf(g.ux) + fabsf(g.uy));
            float s0 = (MODE == 2) ? extra : 0.f;
            active = (s + he > s0 - CUT) && (s - he < s0 + pile + CUT)
                  && (fabsf(r) - he < WIDTH + CUT);
        }
        if (!active) continue;   // block-uniform

        int lw = (threadIdx.x & 7) << 2;   // 0..28 (float4)
        int lh = threadIdx.x >> 3;         // 0..31
        int x0 = tw + lw, y = th + lh;

        float rho[4] = {1.f, 1.f, 1.f, 1.f};
        if (MODE < 2) {
            float4 v4 = *(const float4*)&occ[b*IMG + y*HW + x0];
            rho[0] = v4.x; rho[1] = v4.y; rho[2] = v4.z; rho[3] = v4.w;
        }
        float acc = 0.f;
        #pragma unroll
        for (int j = 0; j < 4; j++) {
            float x = (float)(x0 + j), yf = (float)y;
            if (MODE == 0) {
                float rx = x - g.p0x, ry = yf - g.p0y;
                float t  = clampf(rx*g.ux + ry*g.uy, 0.f, g.L);
                float ddx = rx - t*g.ux, ddy = ry - t*g.uy;
                float d2 = ddx*ddx + ddy*ddy + EPS;
                float R  = WIDTH + CUT;
                if (d2 < R*R) {
                    float dist = d2 * rsqrtf(d2);
                    acc += rho[j] * __fdividef(1.f, 1.f + __expf(dist - WIDTH));
                }
            } else {
                float qx = x - g.p1x, qy = yf - g.p1y;
                float s  = qx*g.ux + qy*g.uy;
                float r  = qy*g.ux - qx*g.uy;
                float ar = fabsf(r);
                float s0 = (MODE == 2) ? extra : 0.f;
                if (s > s0 - CUT && s < s0 + pile + CUT && ar < WIDTH + CUT) {
                    float den = (1.f + __expf(s0 - s))
                              * (1.f + __expf(s - s0 - pile))
                              * (1.f + __expf(ar - WIDTH));
                    acc += rho[j] * __fdividef(1.f, den);
                }
            }
        }
        tileReduceAdd(acc, (MODE == 0) ? &g_msw[b] : ((MODE == 1) ? &g_ext[b] : &g_dsum[b]));
    }
}

// Final: 128x8 tiles, 256 threads, one float4 per thread. Copy fast-path.
__global__ __launch_bounds__(256) void k_final(const float* __restrict__ occ,
                                               float* __restrict__ out) {
    const float WIDTH = 3.0f, CUT = 16.0f, EPS = 1e-8f;
    int b  = blockIdx.z;
    int w0 = blockIdx.x << 7;   // 0..896 step 128
    int h0 = blockIdx.y << 3;   // 0..1016 step 8
    Geo g = g_geo[b];
    float msw   = g_msw[b];
    float pile  = msw * (1.0f/6.0f);
    float extra = g_ext[b] * (1.0f/6.0f);
    float dnorm = __fdividef(msw, g_dsum[b] + EPS);

    // tile activity (block-uniform)
    float cx = w0 + 63.5f, cy = h0 + 3.5f;
    bool sw_act, dep_act;
    {
        float rx = cx - g.p0x, ry = cy - g.p0y;
        float t  = clampf(rx*g.ux + ry*g.uy, 0.f, g.L);
        float ddx = rx - t*g.ux, ddy = ry - t*g.uy;
        float d2 = ddx*ddx + ddy*ddy;
        float R  = WIDTH + CUT + 65.0f;   // + half-diag of 128x8 tile
        sw_act = d2 < R*R;

        float qx = cx - g.p1x, qy = cy - g.p1y;
        float s  = qx*g.ux + qy*g.uy;
        float r  = qy*g.ux - qx*g.uy;
        float sh = 64.5f*fabsf(g.ux) + 4.5f*fabsf(g.uy);
        float rh = 64.5f*fabsf(g.uy) + 4.5f*fabsf(g.ux);
        float M  = CUT + 6.0f;            // + blur reach
        dep_act = (s + sh > extra - M) && (s - sh < extra + pile + M)
               && (fabsf(r) - rh < WIDTH + M);
    }

    int t  = threadIdx.x;
    int lw = (t & 31) << 2;    // col 0..124
    int lh = t >> 5;           // row 0..7
    int gi = b*IMG + (h0 + lh)*HW + (w0 + lw);
    float4 v = *(const float4*)(occ + gi);

    if (!sw_act && !dep_act) {             // pure copy fast path
        *(float4*)(out + gi) = v;
        return;
    }

    __shared__ float sd [16][136];   // dep_mask with halo 4
    __shared__ float shb[16][128];   // horizontally blurred
    __shared__ float sob[8][128];    // fully blurred * dnorm

    float dep[4] = {0.f, 0.f, 0.f, 0.f};
    if (dep_act) {
        for (int i = t; i < 16*136; i += 256) {
            int r_ = i / 136;
            int c_ = i - r_*136;
            int wx = w0 + c_ - 4, hy = h0 + r_ - 4;
            float val = 0.f;
            if ((unsigned)wx < 1024u && (unsigned)hy < 1024u) {
                float qx = (float)wx - g.p1x, qy = (float)hy - g.p1y;
                float s  = qx*g.ux + qy*g.uy;
                float r  = qy*g.ux - qx*g.uy;
                float ar = fabsf(r);
                if (s > extra - CUT && s < extra + pile + CUT && ar < WIDTH + CUT) {
                    float den = (1.f + __expf(extra - s))
                              * (1.f + __expf(s - extra - pile))
                              * (1.f + __expf(ar - WIDTH));
                    val = __fdividef(1.f, den);
                }
            }
            sd[r_][c_] = val;
        }
        __syncthreads();
        for (int i = t; i < 16*128; i += 256) {
            int r_ = i >> 7, c_ = i & 127;
            float a = 0.f;
            #pragma unroll
            for (int j = 0; j < 9; j++) a = fmaf(KW[j], sd[r_][c_ + j], a);
            shb[r_][c_] = a;
        }
        __syncthreads();
        for (int i = t; i < 8*128; i += 256) {
            int r_ = i >> 7, c_ = i & 127;
            float a = 0.f;
            #pragma unroll
            for (int j = 0; j < 9; j++) a = fmaf(KW[j], shb[r_ + j][c_], a);
            sob[r_][c_] = a * dnorm;
        }
        __syncthreads();
        dep[0] = sob[lh][lw];   dep[1] = sob[lh][lw+1];
        dep[2] = sob[lh][lw+2]; dep[3] = sob[lh][lw+3];
    }

    float in[4] = {v.x, v.y, v.z, v.w};
    float o[4];
    #pragma unroll
    for (int j = 0; j < 4; j++) {
        float x = (float)(w0 + lw + j), y = (float)(h0 + lh);
        float sw = 0.f;
        if (sw_act) {
            float rx = x - g.p0x, ry = y - g.p0y;
            float tt = clampf(rx*g.ux + ry*g.uy, 0.f, g.L);
            float ddx = rx - tt*g.ux, ddy = ry - tt*g.uy;
            float d2 = ddx*ddx + ddy*ddy + EPS;
            float R  = WIDTH + CUT;
            if (d2 < R*R) {
                float dist = d2 * rsqrtf(d2);
                sw = __fdividef(1.f, 1.f + __expf(dist - WIDTH));
            }
        }
        o[j] = in[j]*(1.f - sw) + dep[j];
    }
    *(float4*)(out + gi) = make_float4(o[0], o[1], o[2], o[3]);
}

extern "C" void kernel_launch(void* const* d_in, const int* in_sizes, int n_in,
                              void* d_out, int out_size) {
    const float* occ = (const float*)d_in[0];
    const float* as_ = (const float*)d_in[1];
    const float* ae_ = (const float*)d_in[2];
    float* out = (float*)d_out;

    k_scalars<<<1, 32>>>(as_, ae_);
    k_reduce<0><<<1024, 256>>>(occ);
    k_reduce<1><<<1024, 256>>>(occ);
    k_reduce<2><<<1024, 256>>>(occ);
    k_final<<<dim3(8, 128, NB), 256>>>(occ, out);
}

// round 2
// speedup vs baseline: 1.2305x; 1.2305x over previous
#include <cuda_runtime.h>
#include <math.h>

// ---------------------------------------------------------------------------
// SplatPushModel2 — native-layout pipeline, band-AABB tile enumeration.
//   k_scalars : per-batch geometry + zero accumulators
//   k_reduce<0>: m_swept   (tiles enumerated from segment AABB)
//   k_reduce<1>: existing  (tiles enumerated from probe band AABB)
//   k_reduce<2>: dep_sum   (tiles enumerated from deposit band AABB)
//   k_final   : out = occ*(1-swept) + blur(dep_mask)*dep_norm  (copy fast path)
// Sigmoid cutoff CUT=16 -> dropped terms < 1.2e-7 (tol 1e-3).
// ---------------------------------------------------------------------------

#define NB   16
#define HW   1024
#define IMG  (HW*HW)

__device__ __constant__ float KW[9] = {
    0.00761439f, 0.03607498f, 0.10958593f, 0.21344431f, 0.26655960f,
    0.21344431f, 0.10958593f, 0.03607498f, 0.00761439f
};

struct Geo { float p0x, p0y, p1x, p1y, ux, uy, L, pad; };
__device__ Geo  g_geo[NB];
__device__ float g_msw[NB], g_ext[NB], g_dsum[NB];

__device__ __forceinline__ float clampf(float v, float lo, float hi) {
    return fminf(fmaxf(v, lo), hi);
}

// block-wide (256 thr) sum + atomic add; block-uniform call sites only
__device__ __forceinline__ void tileReduceAdd256(float v, float* dst) {
    __shared__ float sred[8];
    #pragma unroll
    for (int o = 16; o > 0; o >>= 1) v += __shfl_down_sync(0xffffffffu, v, o);
    int lane = threadIdx.x & 31, wp = threadIdx.x >> 5;
    if (lane == 0) sred[wp] = v;
    __syncthreads();
    if (wp == 0) {
        v = (lane < 8) ? sred[lane] : 0.0f;
        #pragma unroll
        for (int o = 4; o > 0; o >>= 1) v += __shfl_down_sync(0xffffffffu, v, o);
        if (lane == 0) atomicAdd(dst, v);
    }
    __syncthreads();
}

__global__ void k_scalars(const float* __restrict__ as_, const float* __restrict__ ae_) {
    int b = threadIdx.x;
    if (b < NB) {
        float p0x = as_[b*3+0], p0y = as_[b*3+1];
        float p1x = ae_[b*3+0], p1y = ae_[b*3+1];
        float dx = p1x - p0x, dy = p1y - p0y;
        float L = sqrtf(dx*dx + dy*dy + 1e-8f);
        float inv = __fdividef(1.0f, L);
        Geo g;
        g.p0x = p0x; g.p0y = p0y; g.p1x = p1x; g.p1y = p1y;
        g.ux = dx*inv; g.uy = dy*inv; g.L = L; g.pad = 0.f;
        g_geo[b] = g;
        g_msw[b] = 0.f; g_ext[b] = 0.f; g_dsum[b] = 0.f;
    }
}

// MODE 0: m_swept; MODE 1: existing (probe); MODE 2: dep_sum (no occ read)
template<int MODE>
__global__ __launch_bounds__(256) void k_reduce(const float* __restrict__ occ) {
    const float WIDTH = 3.0f, CUT = 16.0f, EPS = 1e-8f;
    int b = blockIdx.y;
    Geo g = g_geo[b];
    float pile = 0.f, extra = 0.f;
    if (MODE >= 1) pile  = g_msw[b] * (1.0f/6.0f);
    if (MODE == 2) extra = g_ext[b] * (1.0f/6.0f);

    // ---- analytic AABB of the active band (+ safety margin) ----
    const float M = CUT + 1.5f;
    float xmin, xmax, ymin, ymax;
    if (MODE == 0) {
        xmin = fminf(g.p0x, g.p1x) - (WIDTH + M);
        xmax = fmaxf(g.p0x, g.p1x) + (WIDTH + M);
        ymin = fminf(g.p0y, g.p1y) - (WIDTH + M);
        ymax = fmaxf(g.p0y, g.p1y) + (WIDTH + M);
    } else {
        float s0  = (MODE == 2) ? extra : 0.f;
        float slo = s0 - M, shi = s0 + pile + M;
        float R   = WIDTH + M;
        float ax = g.ux*slo, bx = g.ux*shi;
        float ay = g.uy*slo, by = g.uy*shi;
        xmin = g.p1x + fminf(ax, bx) - fabsf(g.uy)*R;
        xmax = g.p1x + fmaxf(ax, bx) + fabsf(g.uy)*R;
        ymin = g.p1y + fminf(ay, by) - fabsf(g.ux)*R;
        ymax = g.p1y + fmaxf(ay, by) + fabsf(g.ux)*R;
    }
    int tx0 = max(0, ((int)floorf(xmin)) >> 5);
    int ty0 = max(0, ((int)floorf(ymin)) >> 5);
    int tx1 = min(31, ((int)floorf(xmax)) >> 5);
    int ty1 = min(31, ((int)floorf(ymax)) >> 5);
    int nx = tx1 - tx0 + 1, ny = ty1 - ty0 + 1;
    if (nx <= 0 || ny <= 0) return;
    int nt = nx * ny;

    for (int idx = blockIdx.x; idx < nt; idx += gridDim.x) {
        int tw = (tx0 + idx % nx) << 5;
        int th = (ty0 + idx / nx) << 5;

        // rotated-band tile cull (block-uniform)
        float cx = tw + 15.5f, cy = th + 15.5f;
        bool active;
        if (MODE == 0) {
            float rx = cx - g.p0x, ry = cy - g.p0y;
            float t  = clampf(rx*g.ux + ry*g.uy, 0.f, g.L);
            float ddx = rx - t*g.ux, ddy = ry - t*g.uy;
            float d2 = ddx*ddx + ddy*ddy;
            float R  = WIDTH + CUT + 23.0f;   // + tile half-diag
            active = d2 < R*R;
        } else {
            float qx = cx - g.p1x, qy = cy - g.p1y;
            float s  = qx*g.ux + qy*g.uy;
            float r  = qy*g.ux - qx*g.uy;
            float he = 16.5f*(fabsf(g.ux) + fabsf(g.uy));
            float s0 = (MODE == 2) ? extra : 0.f;
            active = (s + he > s0 - CUT) && (s - he < s0 + pile + CUT)
                  && (fabsf(r) - he < WIDTH + CUT);
        }
        if (!active) continue;   // block-uniform

        int lw = (threadIdx.x & 7) << 2;   // 0..28 (float4)
        int lh = threadIdx.x >> 3;         // 0..31
        int x0 = tw + lw, y = th + lh;

        float rho[4] = {1.f, 1.f, 1.f, 1.f};
        if (MODE < 2) {
            float4 v4 = *(const float4*)&occ[b*IMG + y*HW + x0];
            rho[0] = v4.x; rho[1] = v4.y; rho[2] = v4.z; rho[3] = v4.w;
        }
        float acc = 0.f;
        #pragma unroll
        for (int j = 0; j < 4; j++) {
            float x = (float)(x0 + j), yf = (float)y;
            if (MODE == 0) {
                float rx = x - g.p0x, ry = yf - g.p0y;
                float t  = clampf(rx*g.ux + ry*g.uy, 0.f, g.L);
                float ddx = rx - t*g.ux, ddy = ry - t*g.uy;
                float d2 = ddx*ddx + ddy*ddy + EPS;
                float R  = WIDTH + CUT;
                if (d2 < R*R) {
                    float dist = d2 * rsqrtf(d2);
                    acc += rho[j] * __fdividef(1.f, 1.f + __expf(dist - WIDTH));
                }
            } else {
                float qx = x - g.p1x, qy = yf - g.p1y;
                float s  = qx*g.ux + qy*g.uy;
                float r  = qy*g.ux - qx*g.uy;
                float ar = fabsf(r);
                float s0 = (MODE == 2) ? extra : 0.f;
                if (s > s0 - CUT && s < s0 + pile + CUT && ar < WIDTH + CUT) {
                    float den = (1.f + __expf(s0 - s))
                              * (1.f + __expf(s - s0 - pile))
                              * (1.f + __expf(ar - WIDTH));
                    acc += rho[j] * __fdividef(1.f, den);
                }
            }
        }
        tileReduceAdd256(acc, (MODE == 0) ? &g_msw[b] : ((MODE == 1) ? &g_ext[b] : &g_dsum[b]));
    }
}

// Final: 128x16 tiles, 512 threads, one float4 per thread. Copy fast-path.
__global__ __launch_bounds__(512) void k_final(const float* __restrict__ occ,
                                               float* __restrict__ out) {
    const float WIDTH = 3.0f, CUT = 16.0f, EPS = 1e-8f;
    int b  = blockIdx.z;
    int w0 = blockIdx.x << 7;   // 0..896 step 128
    int h0 = blockIdx.y << 4;   // 0..1008 step 16
    Geo g = g_geo[b];
    float msw   = g_msw[b];
    float pile  = msw * (1.0f/6.0f);
    float extra = g_ext[b] * (1.0f/6.0f);
    float dnorm = __fdividef(msw, g_dsum[b] + EPS);

    // tile activity (block-uniform)
    float cx = w0 + 63.5f, cy = h0 + 7.5f;
    bool sw_act, dep_act;
    {
        float rx = cx - g.p0x, ry = cy - g.p0y;
        float t  = clampf(rx*g.ux + ry*g.uy, 0.f, g.L);
        float ddx = rx - t*g.ux, ddy = ry - t*g.uy;
        float d2 = ddx*ddx + ddy*ddy;
        float R  = WIDTH + CUT + 65.0f;   // + half-diag of 128x16 tile
        sw_act = d2 < R*R;

        float qx = cx - g.p1x, qy = cy - g.p1y;
        float s  = qx*g.ux + qy*g.uy;
        float r  = qy*g.ux - qx*g.uy;
        float sh = 64.5f*fabsf(g.ux) + 8.5f*fabsf(g.uy);
        float rh = 64.5f*fabsf(g.uy) + 8.5f*fabsf(g.ux);
        float M  = CUT + 6.0f;            // + blur reach
        dep_act = (s + sh > extra - M) && (s - sh < extra + pile + M)
               && (fabsf(r) - rh < WIDTH + M);
    }

    int t  = threadIdx.x;
    int lw = (t & 31) << 2;    // col 0..124
    int lh = t >> 5;           // row 0..15
    int gi = b*IMG + (h0 + lh)*HW + (w0 + lw);
    float4 v = *(const float4*)(occ + gi);

    if (!sw_act && !dep_act) {             // pure copy fast path
        *(float4*)(out + gi) = v;
        return;
    }

    __shared__ float sd [24][136];   // dep_mask with halo 4
    __shared__ float shb[24][128];   // horizontally blurred
    __shared__ float sob[16][128];   // fully blurred * dnorm

    float dep[4] = {0.f, 0.f, 0.f, 0.f};
    if (dep_act) {
        for (int i = t; i < 24*136; i += 512) {
            int r_ = i / 136;
            int c_ = i - r_*136;
            int wx = w0 + c_ - 4, hy = h0 + r_ - 4;
            float val = 0.f;
            if ((unsigned)wx < 1024u && (unsigned)hy < 1024u) {
                float qx = (float)wx - g.p1x, qy = (float)hy - g.p1y;
                float s  = qx*g.ux + qy*g.uy;
                float r  = qy*g.ux - qx*g.uy;
                float ar = fabsf(r);
                if (s > extra - CUT && s < extra + pile + CUT && ar < WIDTH + CUT) {
                    float den = (1.f + __expf(extra - s))
                              * (1.f + __expf(s - extra - pile))
                              * (1.f + __expf(ar - WIDTH));
                    val = __fdividef(1.f, den);
                }
            }
            sd[r_][c_] = val;
        }
        __syncthreads();
        for (int i = t; i < 24*128; i += 512) {
            int r_ = i >> 7, c_ = i & 127;
            float a = 0.f;
            #pragma unroll
            for (int j = 0; j < 9; j++) a = fmaf(KW[j], sd[r_][c_ + j], a);
            shb[r_][c_] = a;
        }
        __syncthreads();
        for (int i = t; i < 16*128; i += 512) {
            int r_ = i >> 7, c_ = i & 127;
            float a = 0.f;
            #pragma unroll
            for (int j = 0; j < 9; j++) a = fmaf(KW[j], shb[r_ + j][c_], a);
            sob[r_][c_] = a * dnorm;
        }
        __syncthreads();
        dep[0] = sob[lh][lw];   dep[1] = sob[lh][lw+1];
        dep[2] = sob[lh][lw+2]; dep[3] = sob[lh][lw+3];
    }

    float in[4] = {v.x, v.y, v.z, v.w};
    float o[4];
    #pragma unroll
    for (int j = 0; j < 4; j++) {
        float x = (float)(w0 + lw + j), y = (float)(h0 + lh);
        float sw = 0.f;
        if (sw_act) {
            float rx = x - g.p0x, ry = y - g.p0y;
            float tt = clampf(rx*g.ux + ry*g.uy, 0.f, g.L);
            float ddx = rx - tt*g.ux, ddy = ry - tt*g.uy;
            float d2 = ddx*ddx + ddy*ddy + EPS;
            float R  = WIDTH + CUT;
            if (d2 < R*R) {
                float dist = d2 * rsqrtf(d2);
                sw = __fdividef(1.f, 1.f + __expf(dist - WIDTH));
            }
        }
        o[j] = in[j]*(1.f - sw) + dep[j];
    }
    *(float4*)(out + gi) = make_float4(o[0], o[1], o[2], o[3]);
}

extern "C" void kernel_launch(void* const* d_in, const int* in_sizes, int n_in,
                              void* d_out, int out_size) {
    const float* occ = (const float*)d_in[0];
    const float* as_ = (const float*)d_in[1];
    const float* ae_ = (const float*)d_in[2];
    float* out = (float*)d_out;

    k_scalars<<<1, 32>>>(as_, ae_);
    k_reduce<0><<<dim3(64, NB), 256>>>(occ);
    k_reduce<1><<<dim3(64, NB), 256>>>(occ);
    k_reduce<2><<<dim3(64, NB), 256>>>(occ);
    k_final<<<dim3(8, 64, NB), 512>>>(occ, out);
}